// round 4
// baseline (speedup 1.0000x reference)
#include <cuda_runtime.h>
#include <math.h>

#define NJc 50000
#define NSc 50000
#define Ec  1600000
#define DIMc 256
#define D4c  64
#define Lc   2
#define Bc   1024
#define NNEGc 32
#define NEGRc (NNEGc*Bc)
#define WSZc (Lc*DIMc*DIMc)

typedef unsigned long long u64;

// ---------------- scratch (device globals; no allocation allowed) ----------------
__device__ float g_Ej[NJc*DIMc];
__device__ float g_Es[NSc*DIMc];
__device__ float g_Gj[NJc*DIMc];
__device__ float g_Gs[NSc*DIMc];
__device__ float g_sEj[NJc*DIMc];
__device__ float g_sEs[NSc*DIMc];
__device__ float g_sGj[NJc*DIMc];
__device__ float g_sGs[NSc*DIMc];
__device__ float g_Tje[NJc*DIMc];
__device__ float g_Tjg[NJc*DIMc];
__device__ float g_Tse[NSc*DIMc];
__device__ float g_Tsg[NSc*DIMc];
__device__ int   g_cnt_j[NJc];
__device__ int   g_cnt_s[NSc];
__device__ int   g_ptr_j[NJc+1];
__device__ int   g_ptr_s[NSc+1];
__device__ int   g_cur_j[NJc];
__device__ int   g_cur_s[NSc];
__device__ int   g_ccol_j[Ec];
__device__ float g_cval_j[Ec];
__device__ int   g_ccol_s[Ec];
__device__ float g_cval_s[Ec];
__device__ float g_gjsel[Bc*DIMc];
__device__ float g_ejsel[Bc*DIMc];
__device__ float g_gssel[Bc*DIMc];
__device__ float g_essel[Bc*DIMc];
__device__ float g_negemb[NEGRc*DIMc];
__device__ float g_sumexp_j[Bc];
__device__ float g_sumexp_s[Bc*NNEGc];
__device__ float g_scalars[8];   // [0]=pos_j sum, [1]=pos_s sum, [2]=wsq

// ---------------- f32x2 helpers ----------------
__device__ __forceinline__ u64 dupf(float x) {
    u64 u;
    asm("mov.b64 %0, {%1, %1};" : "=l"(u) : "f"(x));
    return u;
}
__device__ __forceinline__ void unpackf(u64 v, float& lo, float& hi) {
    asm("mov.b64 {%0, %1}, %2;" : "=f"(lo), "=f"(hi) : "l"(v));
}
#define FMA2(d, a, b) asm("fma.rn.f32x2 %0, %1, %2, %0;" : "+l"(d) : "l"(a), "l"(b))

// ---------------- small utility kernels ----------------
__global__ void zero_kernel() {
    int i = blockIdx.x * blockDim.x + threadIdx.x;
    int st = gridDim.x * blockDim.x;
    for (int k = i; k < NJc; k += st) g_cnt_j[k] = 0;
    for (int k = i; k < NSc; k += st) g_cnt_s[k] = 0;
    for (int k = i; k < Bc; k += st) g_sumexp_j[k] = 0.f;
    for (int k = i; k < Bc*NNEGc; k += st) g_sumexp_s[k] = 0.f;
    if (i < 8) g_scalars[i] = 0.f;
}

__global__ void count_kernel(const int* __restrict__ row_j, const int* __restrict__ col_s) {
    int i = blockIdx.x * blockDim.x + threadIdx.x;
    if (i < Ec) {
        atomicAdd(&g_cnt_j[row_j[i]], 1);
        atomicAdd(&g_cnt_s[col_s[i]], 1);
    }
}

// dual single-block exclusive scan: blockIdx.x = 0 -> j arrays, 1 -> s arrays
__global__ void scan2_kernel() {
    const int* cnt = blockIdx.x ? g_cnt_s : g_cnt_j;
    int* ptr = blockIdx.x ? g_ptr_s : g_ptr_j;
    int* cur = blockIdx.x ? g_cur_s : g_cur_j;
    int n = blockIdx.x ? NSc : NJc;
    __shared__ int warp_sums[32];
    __shared__ int s_carry;
    int tid = threadIdx.x;
    if (tid == 0) { s_carry = 0; ptr[0] = 0; }
    __syncthreads();
    for (int base = 0; base < n; base += 1024) {
        int i = base + tid;
        int v = (i < n) ? cnt[i] : 0;
        int inc = v;
        #pragma unroll
        for (int off = 1; off < 32; off <<= 1) {
            int t = __shfl_up_sync(0xffffffffu, inc, off);
            if ((tid & 31) >= off) inc += t;
        }
        if ((tid & 31) == 31) warp_sums[tid >> 5] = inc;
        __syncthreads();
        if (tid < 32) {
            int ws = warp_sums[tid];
            int wi = ws;
            #pragma unroll
            for (int off = 1; off < 32; off <<= 1) {
                int t = __shfl_up_sync(0xffffffffu, wi, off);
                if (tid >= off) wi += t;
            }
            warp_sums[tid] = wi - ws;   // exclusive warp offset
        }
        __syncthreads();
        int excl = inc - v + warp_sums[tid >> 5];
        int carry = s_carry;
        if (i < n) {
            int start = carry + excl;
            cur[i] = start;
            ptr[i + 1] = start + v;
        }
        __syncthreads();
        if (tid == 1023) s_carry = carry + excl + v;
        __syncthreads();
    }
}

__global__ void scatter_kernel(const int* __restrict__ row_j, const int* __restrict__ col_j,
                               const float* __restrict__ val_j,
                               const int* __restrict__ row_s, const int* __restrict__ col_s,
                               const float* __restrict__ val_s) {
    int i = blockIdx.x * blockDim.x + threadIdx.x;
    if (i >= Ec) return;
    int p = atomicAdd(&g_cur_j[row_j[i]], 1);
    g_ccol_j[p] = col_j[i]; g_cval_j[p] = val_j[i];
    int q = atomicAdd(&g_cur_s[col_s[i]], 1);
    g_ccol_s[q] = row_s[i]; g_cval_s[q] = val_s[i];
}

// ---------------- fused row l2 normalize over up to 4 arrays (blockIdx.y selects) ----------
__global__ void l2norm4_kernel(const float4* s0, float4* d0, const float4* s1, float4* d1,
                               const float4* s2, float4* d2, const float4* s3, float4* d3,
                               int n) {
    const float4* src; float4* dst;
    switch (blockIdx.y) {
        case 0: src = s0; dst = d0; break;
        case 1: src = s1; dst = d1; break;
        case 2: src = s2; dst = d2; break;
        default: src = s3; dst = d3; break;
    }
    int w = (blockIdx.x * blockDim.x + threadIdx.x) >> 5;
    int lane = threadIdx.x & 31;
    if (w >= n) return;
    const float4* s = src + (size_t)w * D4c;
    float4 u0 = s[lane], u1 = s[lane + 32];
    float ss = u0.x*u0.x + u0.y*u0.y + u0.z*u0.z + u0.w*u0.w
             + u1.x*u1.x + u1.y*u1.y + u1.z*u1.z + u1.w*u1.w;
    #pragma unroll
    for (int o = 16; o; o >>= 1) ss += __shfl_xor_sync(0xffffffffu, ss, o);
    float inv = 1.f / fmaxf(sqrtf(ss), 1e-12f);
    float4* d = dst + (size_t)w * D4c;
    d[lane]      = make_float4(u0.x*inv, u0.y*inv, u0.z*inv, u0.w*inv);
    d[lane + 32] = make_float4(u1.x*inv, u1.y*inv, u1.z*inv, u1.w*inv);
}

// ---------------- fused dual SPMM (two independent CSR problems via blockIdx.y) ----------
__device__ __forceinline__ void fma4(float4& acc, float v, const float4& u) {
    acc.x = fmaf(v, u.x, acc.x);
    acc.y = fmaf(v, u.y, acc.y);
    acc.z = fmaf(v, u.z, acc.z);
    acc.w = fmaf(v, u.w, acc.w);
}

__global__ __launch_bounds__(256) void spmm_dual2_kernel(
    const int* __restrict__ ptrA, const int* __restrict__ colsA, const float* __restrict__ valsA,
    const float4* __restrict__ XA1, const float4* __restrict__ XA2,
    float4* __restrict__ OA1, float4* __restrict__ OA2,
    const int* __restrict__ ptrB, const int* __restrict__ colsB, const float* __restrict__ valsB,
    const float4* __restrict__ XB1, const float4* __restrict__ XB2,
    float4* __restrict__ OB1, float4* __restrict__ OB2, int n)
{
    const int *ptr, *cols; const float* vals;
    const float4 *X1, *X2; float4 *O1, *O2;
    if (blockIdx.y == 0) { ptr = ptrA; cols = colsA; vals = valsA; X1 = XA1; X2 = XA2; O1 = OA1; O2 = OA2; }
    else                 { ptr = ptrB; cols = colsB; vals = valsB; X1 = XB1; X2 = XB2; O1 = OB1; O2 = OB2; }
    int w = (blockIdx.x * blockDim.x + threadIdx.x) >> 5;
    int lane = threadIdx.x & 31;
    if (w >= n) return;
    int s = ptr[w], e = ptr[w + 1];
    float4 z = make_float4(0.f, 0.f, 0.f, 0.f);
    float4 a0 = z, a1 = z, b0 = z, b1 = z;
    int p = s;
    for (; p + 2 <= e; p += 2) {
        int c0 = cols[p], c1 = cols[p + 1];
        float v0 = vals[p], v1 = vals[p + 1];
        const float4* x10 = X1 + (size_t)c0 * D4c;
        const float4* x20 = X2 + (size_t)c0 * D4c;
        const float4* x11 = X1 + (size_t)c1 * D4c;
        const float4* x21 = X2 + (size_t)c1 * D4c;
        float4 p0 = x10[lane], p1 = x10[lane + 32];
        float4 q0 = x20[lane], q1 = x20[lane + 32];
        float4 r0 = x11[lane], r1 = x11[lane + 32];
        float4 t0 = x21[lane], t1 = x21[lane + 32];
        fma4(a0, v0, p0); fma4(a1, v0, p1); fma4(b0, v0, q0); fma4(b1, v0, q1);
        fma4(a0, v1, r0); fma4(a1, v1, r1); fma4(b0, v1, t0); fma4(b1, v1, t1);
    }
    if (p < e) {
        int c0 = cols[p]; float v0 = vals[p];
        const float4* x10 = X1 + (size_t)c0 * D4c;
        const float4* x20 = X2 + (size_t)c0 * D4c;
        float4 p0 = x10[lane], p1 = x10[lane + 32];
        float4 q0 = x20[lane], q1 = x20[lane + 32];
        fma4(a0, v0, p0); fma4(a1, v0, p1); fma4(b0, v0, q0); fma4(b1, v0, q1);
    }
    O1[(size_t)w * D4c + lane] = a0; O1[(size_t)w * D4c + 32 + lane] = a1;
    O2[(size_t)w * D4c + lane] = b0; O2[(size_t)w * D4c + 32 + lane] = b1;
}

// ---------------- f32x2 SGEMM 128x128x16 (NT) + fused update epilogue ----------
// out = old + relu(C); sum = first ? old + out : sum + out
// A rows stored DUPLICATED in smem so the broadcast operand is a natural LDS.64 (a,a).
__global__ __launch_bounds__(256, 2) void gemm_update_kernel(
    const float* __restrict__ A, const float* __restrict__ W,
    const float* __restrict__ oldv, float* __restrict__ outv, float* __restrict__ sumv,
    int M, int first)
{
    __shared__ float As2[16][256];   // duplicated: [k][2r] == [k][2r+1]
    __shared__ float Bs[16][128];
    int tid = threadIdx.x;
    int tx = tid & 15, ty = tid >> 4;
    int rowTile = blockIdx.y * 128;
    int colTile = blockIdx.x * 128;
    u64 acc2[8][4];
    #pragma unroll
    for (int i = 0; i < 8; i++)
        #pragma unroll
        for (int p = 0; p < 4; p++) acc2[i][p] = 0ull;

    int lrow = tid & 127;
    int khalf = (tid >> 7) * 8;
    const float* Ag = A + (size_t)(rowTile + lrow) * DIMc + khalf;
    const float* Wg = W + (size_t)(colTile + lrow) * DIMc + khalf;
    bool arow_ok = (rowTile + lrow) < M;
    const float4 z4 = make_float4(0.f, 0.f, 0.f, 0.f);

    for (int k0 = 0; k0 < DIMc; k0 += 16) {
        float4 ra0 = arow_ok ? *(const float4*)(Ag + k0) : z4;
        float4 ra1 = arow_ok ? *(const float4*)(Ag + k0 + 4) : z4;
        float4 rb0 = *(const float4*)(Wg + k0);
        float4 rb1 = *(const float4*)(Wg + k0 + 4);
        __syncthreads();
        *(u64*)&As2[khalf+0][2*lrow] = dupf(ra0.x);
        *(u64*)&As2[khalf+1][2*lrow] = dupf(ra0.y);
        *(u64*)&As2[khalf+2][2*lrow] = dupf(ra0.z);
        *(u64*)&As2[khalf+3][2*lrow] = dupf(ra0.w);
        *(u64*)&As2[khalf+4][2*lrow] = dupf(ra1.x);
        *(u64*)&As2[khalf+5][2*lrow] = dupf(ra1.y);
        *(u64*)&As2[khalf+6][2*lrow] = dupf(ra1.z);
        *(u64*)&As2[khalf+7][2*lrow] = dupf(ra1.w);
        Bs[khalf+0][lrow] = rb0.x; Bs[khalf+1][lrow] = rb0.y;
        Bs[khalf+2][lrow] = rb0.z; Bs[khalf+3][lrow] = rb0.w;
        Bs[khalf+4][lrow] = rb1.x; Bs[khalf+5][lrow] = rb1.y;
        Bs[khalf+6][lrow] = rb1.z; Bs[khalf+7][lrow] = rb1.w;
        __syncthreads();
        #pragma unroll
        for (int kk = 0; kk < 16; kk++) {
            u64 a2[8], b2[4];
            #pragma unroll
            for (int i = 0; i < 4; i++) {
                a2[i]   = *(const u64*)&As2[kk][2*(ty*4 + i)];
                a2[i+4] = *(const u64*)&As2[kk][2*(ty*4 + i + 64)];
            }
            b2[0] = *(const u64*)&Bs[kk][tx*4];
            b2[1] = *(const u64*)&Bs[kk][tx*4 + 2];
            b2[2] = *(const u64*)&Bs[kk][tx*4 + 64];
            b2[3] = *(const u64*)&Bs[kk][tx*4 + 66];
            #pragma unroll
            for (int i = 0; i < 8; i++)
                #pragma unroll
                for (int p = 0; p < 4; p++)
                    FMA2(acc2[i][p], a2[i], b2[p]);
        }
    }
    #pragma unroll
    for (int i = 0; i < 8; i++) {
        int gr = rowTile + ty*4 + (i & 3) + ((i >> 2) * 64);
        if (gr < M) {
            #pragma unroll
            for (int p = 0; p < 4; p++) {
                int gc = colTile + tx*4 + (p & 1)*2 + (p >> 1)*64;
                size_t idx = (size_t)gr * DIMc + gc;
                float lo, hi;
                unpackf(acc2[i][p], lo, hi);
                float2 o2 = *(const float2*)(oldv + idx);
                float2 nv;
                nv.x = o2.x + fmaxf(lo, 0.f);
                nv.y = o2.y + fmaxf(hi, 0.f);
                *(float2*)(outv + idx) = nv;
                float2 sv;
                if (first) { sv.x = o2.x + nv.x; sv.y = o2.y + nv.y; }
                else { float2 s2 = *(const float2*)(sumv + idx); sv.x = s2.x + nv.x; sv.y = s2.y + nv.y; }
                *(float2*)(sumv + idx) = sv;
            }
        }
    }
}

// ---------------- f32x2 GEMM + exp + per-(row,group) sum ----------------
__global__ __launch_bounds__(256, 2) void expsum_kernel(
    const float* __restrict__ A, const float* __restrict__ Bm,
    float* __restrict__ sumexp, int ngroups)
{
    __shared__ float As2[16][256];
    __shared__ float Bs[16][128];
    __shared__ float red[128];
    int tid = threadIdx.x;
    int tx = tid & 15, ty = tid >> 4;
    int rowTile = blockIdx.y * 128;
    int colTile = blockIdx.x * 128;
    u64 acc2[8][4];
    #pragma unroll
    for (int i = 0; i < 8; i++)
        #pragma unroll
        for (int p = 0; p < 4; p++) acc2[i][p] = 0ull;

    int lrow = tid & 127;
    int khalf = (tid >> 7) * 8;
    const float* Ag = A + (size_t)(rowTile + lrow) * DIMc + khalf;
    const float* Bg = Bm + (size_t)(colTile + lrow) * DIMc + khalf;

    for (int k0 = 0; k0 < DIMc; k0 += 16) {
        float4 ra0 = *(const float4*)(Ag + k0);
        float4 ra1 = *(const float4*)(Ag + k0 + 4);
        float4 rb0 = *(const float4*)(Bg + k0);
        float4 rb1 = *(const float4*)(Bg + k0 + 4);
        __syncthreads();
        *(u64*)&As2[khalf+0][2*lrow] = dupf(ra0.x);
        *(u64*)&As2[khalf+1][2*lrow] = dupf(ra0.y);
        *(u64*)&As2[khalf+2][2*lrow] = dupf(ra0.z);
        *(u64*)&As2[khalf+3][2*lrow] = dupf(ra0.w);
        *(u64*)&As2[khalf+4][2*lrow] = dupf(ra1.x);
        *(u64*)&As2[khalf+5][2*lrow] = dupf(ra1.y);
        *(u64*)&As2[khalf+6][2*lrow] = dupf(ra1.z);
        *(u64*)&As2[khalf+7][2*lrow] = dupf(ra1.w);
        Bs[khalf+0][lrow] = rb0.x; Bs[khalf+1][lrow] = rb0.y;
        Bs[khalf+2][lrow] = rb0.z; Bs[khalf+3][lrow] = rb0.w;
        Bs[khalf+4][lrow] = rb1.x; Bs[khalf+5][lrow] = rb1.y;
        Bs[khalf+6][lrow] = rb1.z; Bs[khalf+7][lrow] = rb1.w;
        __syncthreads();
        #pragma unroll
        for (int kk = 0; kk < 16; kk++) {
            u64 a2[8], b2[4];
            #pragma unroll
            for (int i = 0; i < 4; i++) {
                a2[i]   = *(const u64*)&As2[kk][2*(ty*4 + i)];
                a2[i+4] = *(const u64*)&As2[kk][2*(ty*4 + i + 64)];
            }
            b2[0] = *(const u64*)&Bs[kk][tx*4];
            b2[1] = *(const u64*)&Bs[kk][tx*4 + 2];
            b2[2] = *(const u64*)&Bs[kk][tx*4 + 64];
            b2[3] = *(const u64*)&Bs[kk][tx*4 + 66];
            #pragma unroll
            for (int i = 0; i < 8; i++)
                #pragma unroll
                for (int p = 0; p < 4; p++)
                    FMA2(acc2[i][p], a2[i], b2[p]);
        }
    }
    // exp + per-row partial sums
    float rsum[8];
    #pragma unroll
    for (int i = 0; i < 8; i++) {
        rsum[i] = 0.f;
        #pragma unroll
        for (int p = 0; p < 4; p++) {
            float lo, hi;
            unpackf(acc2[i][p], lo, hi);
            rsum[i] += expf(lo * 5.0f) + expf(hi * 5.0f);   // 1/TEMP = 5
        }
    }
    if (tid < 128) red[tid] = 0.f;
    __syncthreads();
    #pragma unroll
    for (int i = 0; i < 8; i++) {
        int r = ty*4 + (i & 3) + ((i >> 2) * 64);
        atomicAdd(&red[r], rsum[i]);
    }
    __syncthreads();
    if (tid < 128) {
        int gr = rowTile + tid;
        int group = blockIdx.x >> 3;   // 128 cols/tile, 1024 cols/group
        atomicAdd(&sumexp[(size_t)gr * ngroups + group], red[tid]);
    }
}

// ---------------- gathers (blockIdx.y selects one of 4 dst/src pairs) ----------------
__global__ void gather4_kernel(const int* __restrict__ j_ids, const int* __restrict__ s_ids) {
    float4* dst; const float4* src; const int* ids;
    switch (blockIdx.y) {
        case 0: dst = (float4*)g_gjsel; src = (const float4*)g_sGj; ids = j_ids; break;
        case 1: dst = (float4*)g_ejsel; src = (const float4*)g_sEj; ids = j_ids; break;
        case 2: dst = (float4*)g_gssel; src = (const float4*)g_sGs; ids = s_ids; break;
        default: dst = (float4*)g_essel; src = (const float4*)g_sEs; ids = s_ids; break;
    }
    int row = blockIdx.x;
    int id = ids[row];
    dst[(size_t)row * D4c + threadIdx.x] = src[(size_t)id * D4c + threadIdx.x];
}

__global__ void gather_kernel(float4* __restrict__ dst, const float4* __restrict__ src,
                              const int* __restrict__ ids) {
    int row = blockIdx.x;
    int id = ids[row];
    dst[(size_t)row * D4c + threadIdx.x] = src[(size_t)id * D4c + threadIdx.x];
}

// ---------------- pos score ----------------
__global__ void pos_kernel() {
    int w = (blockIdx.x * blockDim.x + threadIdx.x) >> 5;
    int lane = threadIdx.x & 31;
    if (w >= Bc) return;
    const float4* gj = (const float4*)g_gjsel + (size_t)w * D4c;
    const float4* ej = (const float4*)g_ejsel + (size_t)w * D4c;
    const float4* gs = (const float4*)g_gssel + (size_t)w * D4c;
    const float4* es = (const float4*)g_essel + (size_t)w * D4c;
    float4 a0 = gj[lane], a1 = gj[lane+32], b0 = ej[lane], b1 = ej[lane+32];
    float4 c0 = gs[lane], c1 = gs[lane+32], d0 = es[lane], d1 = es[lane+32];
    float s1 = a0.x*b0.x + a0.y*b0.y + a0.z*b0.z + a0.w*b0.w
             + a1.x*b1.x + a1.y*b1.y + a1.z*b1.z + a1.w*b1.w;
    float s2 = c0.x*d0.x + c0.y*d0.y + c0.z*d0.z + c0.w*d0.w
             + c1.x*d1.x + c1.y*d1.y + c1.z*d1.z + c1.w*d1.w;
    #pragma unroll
    for (int o = 16; o; o >>= 1) {
        s1 += __shfl_xor_sync(0xffffffffu, s1, o);
        s2 += __shfl_xor_sync(0xffffffffu, s2, o);
    }
    if (lane == 0) {
        float c1v = fminf(fmaxf(s1 * 5.0f, -1.f), 1.f);
        float c2v = fminf(fmaxf(s2 * 5.0f, -1.f), 1.f);
        atomicAdd(&g_scalars[0], c1v);
        atomicAdd(&g_scalars[1], c2v);
    }
}

// ---------------- weight L2 regularizer ----------------
__global__ void wsq_kernel(const float* __restrict__ a, const float* __restrict__ b,
                           const float* __restrict__ c, const float* __restrict__ d) {
    float s = 0.f;
    for (int i = blockIdx.x * blockDim.x + threadIdx.x; i < WSZc; i += gridDim.x * blockDim.x) {
        float x;
        x = a[i]; s += x * x;
        x = b[i]; s += x * x;
        x = c[i]; s += x * x;
        x = d[i]; s += x * x;
    }
    #pragma unroll
    for (int o = 16; o; o >>= 1) s += __shfl_xor_sync(0xffffffffu, s, o);
    __shared__ float sh[8];
    int lane = threadIdx.x & 31, wid = threadIdx.x >> 5;
    if (lane == 0) sh[wid] = s;
    __syncthreads();
    if (threadIdx.x == 0) {
        float t = 0.f;
        for (int i = 0; i < (int)(blockDim.x >> 5); i++) t += sh[i];
        atomicAdd(&g_scalars[2], t);
    }
}

// ---------------- finalize ----------------
__device__ double blk_reduce_1024(double v) {
    __shared__ double sh[32];
    __syncthreads();
    int lane = threadIdx.x & 31, wid = threadIdx.x >> 5;
    #pragma unroll
    for (int o = 16; o; o >>= 1) v += __shfl_down_sync(0xffffffffu, v, o);
    if (lane == 0) sh[wid] = v;
    __syncthreads();
    v = (threadIdx.x < 32) ? sh[threadIdx.x] : 0.0;
    if (wid == 0) {
        #pragma unroll
        for (int o = 16; o; o >>= 1) v += __shfl_down_sync(0xffffffffu, v, o);
    }
    return v;  // valid on thread 0
}

__global__ void finalize_kernel(float* __restrict__ out) {
    int tid = threadIdx.x;
    double a = (tid < Bc) ? log((double)g_sumexp_j[tid] + 1e-8) : 0.0;
    double negj = blk_reduce_1024(a);
    double b = 0.0;
    for (int i = tid; i < Bc * NNEGc; i += 1024)
        b += log((double)g_sumexp_s[i] + 1e-8);
    double negs = blk_reduce_1024(b);
    if (tid == 0) {
        double pos = (double)g_scalars[0] / Bc + (double)g_scalars[1] / Bc;
        double neg = negj / Bc + negs / (double)(Bc * NNEGc);
        double cl = (-pos + neg) * 0.2;
        double reg = 1e-4 * (double)g_scalars[2];
        out[0] = (float)(cl + reg);
        out[1] = (float)cl;
        out[2] = (float)reg;
    }
}

// ---------------- launch ----------------
#define SYM(p, s) do { void* _t = 0; cudaGetSymbolAddress(&_t, s); p = (decltype(p))_t; } while (0)

extern "C" void kernel_launch(void* const* d_in, const int* in_sizes, int n_in,
                              void* d_out, int out_size) {
    (void)in_sizes; (void)n_in; (void)out_size;
    const float* e_j_f   = (const float*)d_in[0];
    const float* e_s_f   = (const float*)d_in[1];
    const float* aug_e_j = (const float*)d_in[2];
    const float* aug_e_s = (const float*)d_in[3];
    const float* val_j   = (const float*)d_in[4];
    const float* val_s   = (const float*)d_in[5];
    const float* W_j     = (const float*)d_in[6];
    const float* W_s     = (const float*)d_in[7];
    const float* W_j_aug = (const float*)d_in[8];
    const float* W_s_aug = (const float*)d_in[9];
    const int* row_j = (const int*)d_in[10];
    const int* col_j = (const int*)d_in[11];
    const int* row_s = (const int*)d_in[12];
    const int* col_s = (const int*)d_in[13];
    const int* j_ids = (const int*)d_in[14];
    const int* s_ids = (const int*)d_in[15];
    const int* negs  = (const int*)d_in[16];
    float* out = (float*)d_out;

    float *Ej, *Es, *Gj, *Gs, *sEj, *sEs, *sGj, *sGs;
    float *Tje, *Tjg, *Tse, *Tsg;
    int *ptr_j, *ptr_s, *ccol_j, *ccol_s;
    float *cval_j, *cval_s;
    float *gjsel, *ejsel, *gssel, *essel, *negemb, *sumexp_j, *sumexp_s;
    SYM(Ej, g_Ej); SYM(Es, g_Es); SYM(Gj, g_Gj); SYM(Gs, g_Gs);
    SYM(sEj, g_sEj); SYM(sEs, g_sEs); SYM(sGj, g_sGj); SYM(sGs, g_sGs);
    SYM(Tje, g_Tje); SYM(Tjg, g_Tjg); SYM(Tse, g_Tse); SYM(Tsg, g_Tsg);
    SYM(ptr_j, g_ptr_j); SYM(ptr_s, g_ptr_s);
    SYM(ccol_j, g_ccol_j); SYM(ccol_s, g_ccol_s);
    SYM(cval_j, g_cval_j); SYM(cval_s, g_cval_s);
    SYM(gjsel, g_gjsel); SYM(ejsel, g_ejsel); SYM(gssel, g_gssel); SYM(essel, g_essel);
    SYM(negemb, g_negemb); SYM(sumexp_j, g_sumexp_j); SYM(sumexp_s, g_sumexp_s);

    const int EB = (Ec + 255) / 256;         // 6250
    const int RB = (NJc * 32 + 255) / 256;   // warp-per-row blocks: 6250

    zero_kernel<<<256, 256>>>();
    count_kernel<<<EB, 256>>>(row_j, col_s);
    scan2_kernel<<<2, 1024>>>();
    scatter_kernel<<<EB, 256>>>(row_j, col_j, val_j, row_s, col_s, val_s);

    {   // initial l2norm of aug embeddings (2 arrays in one launch)
        dim3 g(RB, 2);
        l2norm4_kernel<<<g, 256>>>((const float4*)aug_e_j, (float4*)Gj,
                                   (const float4*)aug_e_s, (float4*)Gs,
                                   (const float4*)aug_e_j, (float4*)Gj,
                                   (const float4*)aug_e_s, (float4*)Gs, NJc);
    }

    dim3 gemm_grid(2, (NJc + 127) / 128);    // N=256 -> 2 col tiles, 391 row tiles
    dim3 spmm_grid(RB, 2);
    for (int l = 0; l < Lc; l++) {
        const float* EjSrc = l ? Ej : e_j_f;
        const float* EsSrc = l ? Es : e_s_f;
        spmm_dual2_kernel<<<spmm_grid, 256>>>(
            ptr_j, ccol_j, cval_j, (const float4*)EsSrc, (const float4*)Gs,
            (float4*)Tje, (float4*)Tjg,
            ptr_s, ccol_s, cval_s, (const float4*)EjSrc, (const float4*)Gj,
            (float4*)Tse, (float4*)Tsg, NJc);
        gemm_update_kernel<<<gemm_grid, 256>>>(Tje, W_j     + l*DIMc*DIMc, EjSrc, Ej, sEj, NJc, l == 0);
        gemm_update_kernel<<<gemm_grid, 256>>>(Tse, W_s     + l*DIMc*DIMc, EsSrc, Es, sEs, NSc, l == 0);
        gemm_update_kernel<<<gemm_grid, 256>>>(Tjg, W_j_aug + l*DIMc*DIMc, Gj,    Gj, sGj, NJc, l == 0);
        gemm_update_kernel<<<gemm_grid, 256>>>(Tsg, W_s_aug + l*DIMc*DIMc, Gs,    Gs, sGs, NSc, l == 0);
    }

    {   // final normalize (scale 1/(L+1) cancels in l2norm) — in place, 4 arrays one launch
        dim3 g(RB, 4);
        l2norm4_kernel<<<g, 256>>>((const float4*)sEj, (float4*)sEj,
                                   (const float4*)sEs, (float4*)sEs,
                                   (const float4*)sGj, (float4*)sGj,
                                   (const float4*)sGs, (float4*)sGs, NJc);
    }

    {
        dim3 g(Bc, 4);
        gather4_kernel<<<g, 64>>>(j_ids, s_ids);
    }
    gather_kernel<<<NEGRc, 64>>>((float4*)negemb, (const float4*)sEs, negs);

    dim3 lg(Bc / 128, Bc / 128);             // 8 x 8
    expsum_kernel<<<lg, 256>>>(gjsel, ejsel, sumexp_j, 1);
    dim3 ng(NEGRc / 128, Bc / 128);          // 256 x 8
    expsum_kernel<<<ng, 256>>>(gssel, negemb, sumexp_s, NNEGc);

    pos_kernel<<<Bc / 8, 256>>>();
    wsq_kernel<<<256, 256>>>(W_j, W_s, W_j_aug, W_s_aug);
    finalize_kernel<<<1, 1024>>>(out);
}